// round 1
// baseline (speedup 1.0000x reference)
#include <cuda_runtime.h>
#include <math.h>

#define N_NODES 10000
#define N_EDGES 160000
#define FEAT_DIM 320
#define AGG_DIM 768

// Scratch (device globals: allocation-free rule)
__device__ float g_feat[N_NODES * FEAT_DIM];  // [n][0:128]=feat0, [128+u*3+i]=feat1
__device__ float g_self[N_NODES * FEAT_DIM];  // same layout
__device__ float g_agg [N_NODES * AGG_DIM];   // segment-summed edge_mid (unscaled)

__device__ __forceinline__ float gelu_tanh(float x) {
    // jax.nn.gelu(approximate=True)
    float x3 = x * x * x;
    float t  = tanhf(0.7978845608028654f * (x + 0.044715f * x3));
    return 0.5f * x * (1.0f + t);
}

__device__ __forceinline__ void red4(float* p, float4 v) {
    asm volatile("red.global.add.v4.f32 [%0], {%1,%2,%3,%4};"
                 :: "l"(p), "f"(v.x), "f"(v.y), "f"(v.z), "f"(v.w) : "memory");
}

// ---------------------------------------------------------------------------
// Kernel A: node pre-transforms. 32 nodes/block, 256 threads.
// feat0 = x0@Wa0/sqrt(128); feat1[u,i] = sum_v x1[v,i] Wa1[v,u]/sqrt(64); same for self (Wb).
// ---------------------------------------------------------------------------
__global__ void __launch_bounds__(256) node_pre_kernel(
    const float* __restrict__ node,
    const float* __restrict__ Wa0, const float* __restrict__ Wa1,
    const float* __restrict__ Wb0, const float* __restrict__ Wb1)
{
    extern __shared__ float sm[];
    float* xT = sm;              // 320 x 33 (padded), transposed input tile
    float* sW = sm + 320 * 33;   // up to 128*64 weight chunk
    const int tid = threadIdx.x;
    const int nb  = blockIdx.x * 32;

    for (int idx = tid; idx < 32 * 320; idx += 256) {
        int n = idx / 320, k = idx % 320;
        float v = (nb + n < N_NODES) ? node[(nb + n) * 320 + k] : 0.f;
        xT[k * 33 + n] = v;
    }

    const int np = tid >> 4;    // 0..15
    const int uq = tid & 15;    // 0..15
    const int n0 = np * 2, u0 = uq * 4;

    // scalar parts (128 -> 128), two weights, two u-chunks
    for (int w = 0; w < 2; ++w) {
        const float* W  = w ? Wb0 : Wa0;
        float* dst      = w ? g_self : g_feat;
        for (int uc = 0; uc < 128; uc += 64) {
            __syncthreads();
            for (int idx = tid; idx < 128 * 64; idx += 256) {
                int k = idx >> 6, u = idx & 63;
                sW[idx] = W[k * 128 + uc + u];
            }
            __syncthreads();
            float acc[2][4] = {};
            #pragma unroll 8
            for (int k = 0; k < 128; ++k) {
                float a0 = xT[k * 33 + n0];
                float a1 = xT[k * 33 + n0 + 1];
                float4 b = *(const float4*)&sW[k * 64 + u0];
                acc[0][0] += a0 * b.x; acc[0][1] += a0 * b.y;
                acc[0][2] += a0 * b.z; acc[0][3] += a0 * b.w;
                acc[1][0] += a1 * b.x; acc[1][1] += a1 * b.y;
                acc[1][2] += a1 * b.z; acc[1][3] += a1 * b.w;
            }
            const float sc = 0.08838834764831845f;  // 1/sqrt(128)
            #pragma unroll
            for (int j = 0; j < 2; ++j) {
                int n = nb + n0 + j;
                if (n < N_NODES) {
                    float4 o = make_float4(acc[j][0]*sc, acc[j][1]*sc, acc[j][2]*sc, acc[j][3]*sc);
                    *(float4*)&dst[n * 320 + uc + u0] = o;
                }
            }
        }
    }
    // vector parts (64x3 -> 64x3)
    for (int w = 0; w < 2; ++w) {
        const float* W  = w ? Wb1 : Wa1;
        float* dst      = w ? g_self : g_feat;
        __syncthreads();
        for (int idx = tid; idx < 64 * 64; idx += 256) sW[idx] = W[idx];
        __syncthreads();
        for (int i = 0; i < 3; ++i) {
            float acc[2][4] = {};
            #pragma unroll 8
            for (int v = 0; v < 64; ++v) {
                float a0 = xT[(128 + v * 3 + i) * 33 + n0];
                float a1 = xT[(128 + v * 3 + i) * 33 + n0 + 1];
                float4 b = *(const float4*)&sW[v * 64 + u0];
                acc[0][0] += a0 * b.x; acc[0][1] += a0 * b.y;
                acc[0][2] += a0 * b.z; acc[0][3] += a0 * b.w;
                acc[1][0] += a1 * b.x; acc[1][1] += a1 * b.y;
                acc[1][2] += a1 * b.z; acc[1][3] += a1 * b.w;
            }
            const float sc = 0.125f;  // 1/sqrt(64)
            #pragma unroll
            for (int j = 0; j < 2; ++j) {
                int n = nb + n0 + j;
                if (n < N_NODES) {
                    #pragma unroll
                    for (int q = 0; q < 4; ++q)
                        dst[n * 320 + 128 + (u0 + q) * 3 + i] = acc[j][q] * sc;
                }
            }
        }
    }
}

// ---------------------------------------------------------------------------
// Kernel B: edge MLP + tensor product + scatter-add. 64 edges/block, 256 threads.
// ---------------------------------------------------------------------------
__global__ void __launch_bounds__(256) edge_kernel(
    const float* __restrict__ edge_attr, const float* __restrict__ esa,
    const float* __restrict__ M1, const float* __restrict__ M2,
    const float* __restrict__ Wtp0, const float* __restrict__ Wtp1,
    const float* __restrict__ Wtp2, const float* __restrict__ Wtp3,
    const int* __restrict__ esrc, const int* __restrict__ edst)
{
    extern __shared__ float sm[];
    float* sInT = sm;             // 8 x 64   (transposed edge scalars)
    float* sH1T = sm + 512;       // 64 x 64  [chan][edge]
    float* sH2T = sH1T + 4096;    // 64 x 64  [chan][edge]
    float* sW   = sH2T + 4096;    // 64 x 128 (weight stage: M2 then Wtp_p)
    float* sWP  = sW + 8192;      // 64 x 128 (w outputs [edge][u])
    int*   sSrc = (int*)(sWP + 8192);    // 64
    int*   sDst = sSrc + 64;             // 64
    float* sY   = (float*)(sDst + 64);   // 64 x 4

    const int tid = threadIdx.x;
    const int eb  = blockIdx.x * 64;

    for (int idx = tid; idx < 64 * 8; idx += 256) {
        int e = idx >> 3, k = idx & 7;
        sInT[k * 64 + e] = esa[(eb + e) * 8 + k];
    }
    if (tid < 64) {
        sSrc[tid] = esrc[eb + tid];
        sDst[tid] = edst[eb + tid];
        float4 y = *(const float4*)&edge_attr[(eb + tid) * 4];
        sY[tid * 4 + 0] = y.x; sY[tid * 4 + 1] = y.y;
        sY[tid * 4 + 2] = y.z; sY[tid * 4 + 3] = y.w;
    }
    for (int idx = tid; idx < 4096; idx += 256) sW[idx] = M2[idx];
    __syncthreads();

    // h1 = gelu((esa @ M1) / sqrt(8));  layout sH1T[u][e]
    for (int idx = tid; idx < 4096; idx += 256) {
        int u = idx >> 6, e = idx & 63;
        float s = 0.f;
        #pragma unroll
        for (int k = 0; k < 8; ++k) s += sInT[k * 64 + e] * __ldg(&M1[k * 64 + u]);
        sH1T[idx] = gelu_tanh(s * 0.3535533905932738f);
    }
    __syncthreads();

    // h2 = gelu((h1 @ M2) / sqrt(64));  layout sH2T[u][e]
    {
        const int ep = tid & 15, uqv = tid >> 4;
        const int e0 = ep * 4, u0 = uqv * 4;
        float acc[4][4] = {};
        #pragma unroll 8
        for (int k = 0; k < 64; ++k) {
            float4 a = *(const float4*)&sH1T[k * 64 + e0];
            float4 b = *(const float4*)&sW[k * 64 + u0];
            acc[0][0] += a.x*b.x; acc[0][1] += a.x*b.y; acc[0][2] += a.x*b.z; acc[0][3] += a.x*b.w;
            acc[1][0] += a.y*b.x; acc[1][1] += a.y*b.y; acc[1][2] += a.y*b.z; acc[1][3] += a.y*b.w;
            acc[2][0] += a.z*b.x; acc[2][1] += a.z*b.y; acc[2][2] += a.z*b.z; acc[2][3] += a.z*b.w;
            acc[3][0] += a.w*b.x; acc[3][1] += a.w*b.y; acc[3][2] += a.w*b.z; acc[3][3] += a.w*b.w;
        }
        __syncthreads();  // everyone done reading sW(M2) before h2 store / restage
        #pragma unroll
        for (int ei = 0; ei < 4; ++ei)
            #pragma unroll
            for (int uj = 0; uj < 4; ++uj)
                sH2T[(u0 + uj) * 64 + e0 + ei] = gelu_tanh(acc[ei][uj] * 0.125f);
    }
    __syncthreads();

    const int wid = tid >> 5, lane = tid & 31;
    const int lu = lane & 15, sub = lane >> 4;

    for (int p = 0; p < 4; ++p) {
        const int UW = (p < 2) ? 128 : 64;
        const float* Wp = (p == 0) ? Wtp0 : (p == 1) ? Wtp1 : (p == 2) ? Wtp2 : Wtp3;
        for (int idx = tid; idx < 64 * UW; idx += 256) sW[idx] = Wp[idx];
        __syncthreads();

        // w_p = (h2 @ Wtp_p) / sqrt(64);  layout sWP[e][u] stride UW
        const int ntile = (64 * UW) >> 4;
        for (int tt = tid; tt < ntile; tt += 256) {
            int tep = tt & 15, tuq = tt >> 4;
            int te0 = tep * 4, tu0 = tuq * 4;
            float acc[4][4] = {};
            #pragma unroll 8
            for (int k = 0; k < 64; ++k) {
                float4 a = *(const float4*)&sH2T[k * 64 + te0];
                float4 b = *(const float4*)&sW[k * UW + tu0];
                acc[0][0] += a.x*b.x; acc[0][1] += a.x*b.y; acc[0][2] += a.x*b.z; acc[0][3] += a.x*b.w;
                acc[1][0] += a.y*b.x; acc[1][1] += a.y*b.y; acc[1][2] += a.y*b.z; acc[1][3] += a.y*b.w;
                acc[2][0] += a.z*b.x; acc[2][1] += a.z*b.y; acc[2][2] += a.z*b.z; acc[2][3] += a.z*b.w;
                acc[3][0] += a.w*b.x; acc[3][1] += a.w*b.y; acc[3][2] += a.w*b.z; acc[3][3] += a.w*b.w;
            }
            #pragma unroll
            for (int ei = 0; ei < 4; ++ei) {
                float4 o = make_float4(acc[ei][0]*0.125f, acc[ei][1]*0.125f,
                                       acc[ei][2]*0.125f, acc[ei][3]*0.125f);
                *(float4*)&sWP[(te0 + ei) * UW + tu0] = o;
            }
        }
        __syncthreads();

        if (p == 0) {
            // mid0a[u] = w0[u]*e0[u]*y0 -> agg[0:128]
            for (int e = wid * 8; e < wid * 8 + 8; ++e) {
                int src = sSrc[e], dst = sDst[e];
                float y0 = sY[e * 4];
                float4 f = *(const float4*)&g_feat[src * 320 + lane * 4];
                float4 w = *(const float4*)&sWP[e * 128 + lane * 4];
                red4(&g_agg[dst * 768 + lane * 4],
                     make_float4(w.x*f.x*y0, w.y*f.y*y0, w.z*f.z*y0, w.w*f.w*y0));
            }
        } else if (p == 1) {
            // mid1a[u,i] = w1[u]*e0[u]*y1[i] -> agg[192 + u*3+i]
            for (int e = wid * 8; e < wid * 8 + 8; ++e) {
                int src = sSrc[e], dst = sDst[e];
                float ya = sY[e*4+1], yb = sY[e*4+2], yc = sY[e*4+3];
                float4 f = *(const float4*)&g_feat[src * 320 + lane * 4];
                float4 w = *(const float4*)&sWP[e * 128 + lane * 4];
                float t0 = w.x*f.x, t1 = w.y*f.y, t2 = w.z*f.z, t3 = w.w*f.w;
                float* base = &g_agg[dst * 768 + 192 + lane * 12];
                red4(base,     make_float4(t0*ya, t0*yb, t0*yc, t1*ya));
                red4(base + 4, make_float4(t1*yb, t1*yc, t2*ya, t2*yb));
                red4(base + 8, make_float4(t2*yc, t3*ya, t3*yb, t3*yc));
            }
        } else if (p == 2) {
            // mid1b[u,i] = w2[u]*e1[u,i]*y0 -> agg[576 + u*3+i]  (half-warp per edge)
            for (int s = 0; s < 4; ++s) {
                int e = wid * 8 + s * 2 + sub;
                int src = sSrc[e], dst = sDst[e];
                float y0 = sY[e * 4];
                const float* fb = &g_feat[src * 320 + 128 + lu * 12];
                float4 g0 = *(const float4*)fb;
                float4 g1 = *(const float4*)(fb + 4);
                float4 g2 = *(const float4*)(fb + 8);
                float4 w  = *(const float4*)&sWP[e * 64 + lu * 4];
                float* base = &g_agg[dst * 768 + 576 + lu * 12];
                red4(base,     make_float4(w.x*g0.x*y0, w.x*g0.y*y0, w.x*g0.z*y0, w.y*g0.w*y0));
                red4(base + 4, make_float4(w.y*g1.x*y0, w.y*g1.y*y0, w.z*g1.z*y0, w.z*g1.w*y0));
                red4(base + 8, make_float4(w.z*g2.x*y0, w.w*g2.y*y0, w.w*g2.z*y0, w.w*g2.w*y0));
            }
        } else {
            // mid0b[u] = w3[u]*dot(e1[u,:],y1)/sqrt(3) -> agg[128 + u]
            const float is3 = 0.5773502691896258f;
            for (int s = 0; s < 4; ++s) {
                int e = wid * 8 + s * 2 + sub;
                int src = sSrc[e], dst = sDst[e];
                float ya = sY[e*4+1], yb = sY[e*4+2], yc = sY[e*4+3];
                const float* fb = &g_feat[src * 320 + 128 + lu * 12];
                float4 g0 = *(const float4*)fb;
                float4 g1 = *(const float4*)(fb + 4);
                float4 g2 = *(const float4*)(fb + 8);
                float4 w  = *(const float4*)&sWP[e * 64 + lu * 4];
                float d0 = g0.x*ya + g0.y*yb + g0.z*yc;
                float d1 = g0.w*ya + g1.x*yb + g1.y*yc;
                float d2 = g1.z*ya + g1.w*yb + g2.x*yc;
                float d3 = g2.y*ya + g2.z*yb + g2.w*yc;
                red4(&g_agg[dst * 768 + 128 + lu * 4],
                     make_float4(w.x*d0*is3, w.y*d1*is3, w.z*d2*is3, w.w*d3*is3));
            }
        }
        __syncthreads();
    }
}

// ---------------------------------------------------------------------------
// Kernel D: output transforms. 32 nodes/block, 256 threads.
// out0 = c*self0 + s*(agg/4)[:, :192]@Wo0/sqrt(192)
// out1 = c*self1 + s*einsum((agg/4) z1, Wo1)/sqrt(192)
// ---------------------------------------------------------------------------
__global__ void __launch_bounds__(256) node_out_kernel(
    const float* __restrict__ Wo0, const float* __restrict__ Wo1,
    float* __restrict__ out)
{
    extern __shared__ float sm[];
    float* zT = sm;             // 192 x 33
    float* sW = sm + 192 * 33;  // 192 x 64
    const int tid = threadIdx.x;
    const int nb  = blockIdx.x * 32;
    const int np = tid >> 4, uq = tid & 15;
    const int n0 = np * 2, u0 = uq * 4;
    const float cs    = 0.9238795325112867f;   // cos(pi/8)
    const float kconv = 0.38268343236508984f * 0.25f * 0.07216878364870323f; // s * 1/sqrt(16) * 1/sqrt(192)

    // scalar head: z0 = agg[:, :192]
    for (int idx = tid; idx < 32 * 192; idx += 256) {
        int n = idx / 192, k = idx % 192;
        zT[k * 33 + n] = (nb + n < N_NODES) ? g_agg[(nb + n) * 768 + k] : 0.f;
    }
    for (int uc = 0; uc < 128; uc += 64) {
        __syncthreads();
        for (int idx = tid; idx < 192 * 64; idx += 256) {
            int k = idx >> 6, u = idx & 63;
            sW[idx] = Wo0[k * 128 + uc + u];
        }
        __syncthreads();
        float acc[2][4] = {};
        #pragma unroll 8
        for (int k = 0; k < 192; ++k) {
            float a0 = zT[k * 33 + n0];
            float a1 = zT[k * 33 + n0 + 1];
            float4 b = *(const float4*)&sW[k * 64 + u0];
            acc[0][0] += a0*b.x; acc[0][1] += a0*b.y; acc[0][2] += a0*b.z; acc[0][3] += a0*b.w;
            acc[1][0] += a1*b.x; acc[1][1] += a1*b.y; acc[1][2] += a1*b.z; acc[1][3] += a1*b.w;
        }
        #pragma unroll
        for (int j = 0; j < 2; ++j) {
            int n = nb + n0 + j;
            if (n < N_NODES) {
                const float* sf = &g_self[n * 320 + uc + u0];
                float4 o = make_float4(cs*sf[0] + kconv*acc[j][0],
                                       cs*sf[1] + kconv*acc[j][1],
                                       cs*sf[2] + kconv*acc[j][2],
                                       cs*sf[3] + kconv*acc[j][3]);
                *(float4*)&out[n * 320 + uc + u0] = o;
            }
        }
    }

    // vector head: z1[v,i] = agg[192 + v*3 + i], v < 192
    __syncthreads();
    for (int idx = tid; idx < 192 * 64; idx += 256) sW[idx] = Wo1[idx];
    for (int i = 0; i < 3; ++i) {
        __syncthreads();
        for (int idx = tid; idx < 32 * 192; idx += 256) {
            int n = idx / 192, k = idx % 192;
            zT[k * 33 + n] = (nb + n < N_NODES) ? g_agg[(nb + n) * 768 + 192 + k * 3 + i] : 0.f;
        }
        __syncthreads();
        float acc[2][4] = {};
        #pragma unroll 8
        for (int k = 0; k < 192; ++k) {
            float a0 = zT[k * 33 + n0];
            float a1 = zT[k * 33 + n0 + 1];
            float4 b = *(const float4*)&sW[k * 64 + u0];
            acc[0][0] += a0*b.x; acc[0][1] += a0*b.y; acc[0][2] += a0*b.z; acc[0][3] += a0*b.w;
            acc[1][0] += a1*b.x; acc[1][1] += a1*b.y; acc[1][2] += a1*b.z; acc[1][3] += a1*b.w;
        }
        #pragma unroll
        for (int j = 0; j < 2; ++j) {
            int n = nb + n0 + j;
            if (n < N_NODES) {
                #pragma unroll
                for (int q = 0; q < 4; ++q)
                    out[n * 320 + 128 + (u0 + q) * 3 + i] =
                        cs * g_self[n * 320 + 128 + (u0 + q) * 3 + i] + kconv * acc[j][q];
            }
        }
    }
}

// ---------------------------------------------------------------------------
extern "C" void kernel_launch(void* const* d_in, const int* in_sizes, int n_in,
                              void* d_out, int out_size)
{
    const float* node = (const float*)d_in[0];
    const float* edge_attr = (const float*)d_in[1];
    const float* esa  = (const float*)d_in[2];
    const float* Wa0  = (const float*)d_in[3];
    const float* Wa1  = (const float*)d_in[4];
    const float* Wb0  = (const float*)d_in[5];
    const float* Wb1  = (const float*)d_in[6];
    const float* M1   = (const float*)d_in[7];
    const float* M2   = (const float*)d_in[8];
    const float* Wtp0 = (const float*)d_in[9];
    const float* Wtp1 = (const float*)d_in[10];
    const float* Wtp2 = (const float*)d_in[11];
    const float* Wtp3 = (const float*)d_in[12];
    const float* Wo0  = (const float*)d_in[13];
    const float* Wo1  = (const float*)d_in[14];
    const int* esrc   = (const int*)d_in[15];
    const int* edst   = (const int*)d_in[16];
    float* out = (float*)d_out;

    const int smemA = (320 * 33 + 128 * 64) * 4;                 // 75008
    const int smemB = (512 + 4096 + 4096 + 8192 + 8192) * 4 + 64 * 4 * 2 + 64 * 4 * 4; // 101888
    const int smemD = (192 * 33 + 192 * 64) * 4;                 // 74496

    cudaFuncSetAttribute(node_pre_kernel, cudaFuncAttributeMaxDynamicSharedMemorySize, smemA);
    cudaFuncSetAttribute(edge_kernel,     cudaFuncAttributeMaxDynamicSharedMemorySize, smemB);
    cudaFuncSetAttribute(node_out_kernel, cudaFuncAttributeMaxDynamicSharedMemorySize, smemD);

    void* aggp = nullptr;
    cudaGetSymbolAddress(&aggp, g_agg);
    cudaMemsetAsync(aggp, 0, sizeof(float) * (size_t)N_NODES * AGG_DIM);

    node_pre_kernel<<<(N_NODES + 31) / 32, 256, smemA>>>(node, Wa0, Wa1, Wb0, Wb1);
    edge_kernel<<<N_EDGES / 64, 256, smemB>>>(edge_attr, esa, M1, M2,
                                              Wtp0, Wtp1, Wtp2, Wtp3, esrc, edst);
    node_out_kernel<<<(N_NODES + 31) / 32, 256, smemD>>>(Wo0, Wo1, out);
}

// round 2
// speedup vs baseline: 1.2793x; 1.2793x over previous
#include <cuda_runtime.h>
#include <math.h>

#define N_NODES 10000
#define N_EDGES 160000
#define FEAT_DIM 320
#define AGG_DIM 768

typedef unsigned long long u64;

// Scratch (device globals: allocation-free rule)
__device__ float g_feat[N_NODES * FEAT_DIM];  // [n][0:128]=feat0, [128+u*3+i]=feat1
__device__ float g_self[N_NODES * FEAT_DIM];  // same layout
__device__ float g_agg [N_NODES * AGG_DIM];   // segment-summed edge_mid (unscaled)

__device__ __forceinline__ float gelu_tanh(float x) {
    float x3 = x * x * x;
    float t  = tanhf(0.7978845608028654f * (x + 0.044715f * x3));
    return 0.5f * x * (1.0f + t);
}

__device__ __forceinline__ void red4(float* p, float4 v) {
    asm volatile("red.global.add.v4.f32 [%0], {%1,%2,%3,%4};"
                 :: "l"(p), "f"(v.x), "f"(v.y), "f"(v.z), "f"(v.w) : "memory");
}

// ---- packed f32x2 helpers (Blackwell FFMA2: 2 MACs per issue slot) ----
__device__ __forceinline__ u64 dupf(float x) {
    u64 r; asm("mov.b64 %0, {%1, %1};" : "=l"(r) : "f"(x)); return r;
}
__device__ __forceinline__ void unpack2(u64 v, float& lo, float& hi) {
    asm("mov.b64 {%0, %1}, %2;" : "=f"(lo), "=f"(hi) : "l"(v));
}
#define FFMA2(d, a, b, c) asm("fma.rn.f32x2 %0, %1, %2, %3;" : "=l"(d) : "l"(a), "l"(b), "l"(c))

// ---------------------------------------------------------------------------
// Kernel A: node pre-transforms. 32 nodes/block, 256 threads.
// ---------------------------------------------------------------------------
__global__ void __launch_bounds__(256) node_pre_kernel(
    const float* __restrict__ node,
    const float* __restrict__ Wa0, const float* __restrict__ Wa1,
    const float* __restrict__ Wb0, const float* __restrict__ Wb1)
{
    extern __shared__ float sm[];
    float* xT = sm;               // 320 x 34 (even pad -> aligned u64 node-pairs)
    float* sW = sm + 320 * 34;    // 128 x 128 weight stage
    const int tid = threadIdx.x;
    const int nb  = blockIdx.x * 32;

    for (int idx = tid; idx < 32 * 320; idx += 256) {
        int n = idx / 320, k = idx % 320;
        float v = (nb + n < N_NODES) ? node[(nb + n) * 320 + k] : 0.f;
        xT[k * 34 + n] = v;
    }

    // ---- scalar part: x0(128) @ W(128x128), nodes packed in f32x2 ----
    const int n0s = (tid >> 5) * 4;   // 8 groups x 4 nodes
    const int u0s = (tid & 31) * 4;   // 32 groups x 4 u
    for (int w = 0; w < 2; ++w) {
        const float* W = w ? Wb0 : Wa0;
        float* dst     = w ? g_self : g_feat;
        __syncthreads();
        for (int idx = tid; idx < 4096; idx += 256)
            ((float4*)sW)[idx] = ((const float4*)W)[idx];
        __syncthreads();
        u64 acc[2][4] = {};
        #pragma unroll 4
        for (int k = 0; k < 128; ++k) {
            u64 a01 = *(const u64*)&xT[k * 34 + n0s];
            u64 a23 = *(const u64*)&xT[k * 34 + n0s + 2];
            float4 b = *(const float4*)&sW[k * 128 + u0s];
            u64 b0 = dupf(b.x), b1 = dupf(b.y), b2 = dupf(b.z), b3 = dupf(b.w);
            FFMA2(acc[0][0], a01, b0, acc[0][0]); FFMA2(acc[0][1], a01, b1, acc[0][1]);
            FFMA2(acc[0][2], a01, b2, acc[0][2]); FFMA2(acc[0][3], a01, b3, acc[0][3]);
            FFMA2(acc[1][0], a23, b0, acc[1][0]); FFMA2(acc[1][1], a23, b1, acc[1][1]);
            FFMA2(acc[1][2], a23, b2, acc[1][2]); FFMA2(acc[1][3], a23, b3, acc[1][3]);
        }
        const float sc = 0.08838834764831845f;  // 1/sqrt(128)
        #pragma unroll
        for (int p = 0; p < 2; ++p) {
            float lo[4], hi[4];
            #pragma unroll
            for (int j = 0; j < 4; ++j) unpack2(acc[p][j], lo[j], hi[j]);
            int na = nb + n0s + 2 * p, nc = na + 1;
            if (na < N_NODES)
                *(float4*)&dst[na * 320 + u0s] =
                    make_float4(lo[0]*sc, lo[1]*sc, lo[2]*sc, lo[3]*sc);
            if (nc < N_NODES)
                *(float4*)&dst[nc * 320 + u0s] =
                    make_float4(hi[0]*sc, hi[1]*sc, hi[2]*sc, hi[3]*sc);
        }
    }

    // ---- vector part: both Wa1 (half 0) and Wb1 (half 1) concurrently ----
    __syncthreads();
    for (int idx = tid; idx < 1024; idx += 256) ((float4*)sW)[idx] = ((const float4*)Wa1)[idx];
    for (int idx = tid; idx < 1024; idx += 256) ((float4*)(sW + 4096))[idx] = ((const float4*)Wb1)[idx];
    __syncthreads();
    {
        const int half = tid >> 7;           // 0 -> feat(Wa1), 1 -> self(Wb1)
        const int wt   = tid & 127;
        const int n0   = (wt >> 4) * 4;      // 8 x 4 nodes
        const int u0   = (wt & 15) * 4;      // 16 x 4 u
        const float* sWh = sW + half * 4096;
        float* dst       = half ? g_self : g_feat;
        for (int i = 0; i < 3; ++i) {
            u64 acc[2][4] = {};
            #pragma unroll 4
            for (int v = 0; v < 64; ++v) {
                int k = 128 + v * 3 + i;
                u64 a01 = *(const u64*)&xT[k * 34 + n0];
                u64 a23 = *(const u64*)&xT[k * 34 + n0 + 2];
                float4 b = *(const float4*)&sWh[v * 64 + u0];
                u64 b0 = dupf(b.x), b1 = dupf(b.y), b2 = dupf(b.z), b3 = dupf(b.w);
                FFMA2(acc[0][0], a01, b0, acc[0][0]); FFMA2(acc[0][1], a01, b1, acc[0][1]);
                FFMA2(acc[0][2], a01, b2, acc[0][2]); FFMA2(acc[0][3], a01, b3, acc[0][3]);
                FFMA2(acc[1][0], a23, b0, acc[1][0]); FFMA2(acc[1][1], a23, b1, acc[1][1]);
                FFMA2(acc[1][2], a23, b2, acc[1][2]); FFMA2(acc[1][3], a23, b3, acc[1][3]);
            }
            const float sc = 0.125f;  // 1/sqrt(64)
            #pragma unroll
            for (int p = 0; p < 2; ++p) {
                float lo[4], hi[4];
                #pragma unroll
                for (int j = 0; j < 4; ++j) unpack2(acc[p][j], lo[j], hi[j]);
                int na = nb + n0 + 2 * p, nc = na + 1;
                #pragma unroll
                for (int j = 0; j < 4; ++j) {
                    if (na < N_NODES) dst[na * 320 + 128 + (u0 + j) * 3 + i] = lo[j] * sc;
                    if (nc < N_NODES) dst[nc * 320 + 128 + (u0 + j) * 3 + i] = hi[j] * sc;
                }
            }
        }
    }
}

// ---------------------------------------------------------------------------
// Edge kernel helpers
// ---------------------------------------------------------------------------
template<int UW>
__device__ __forceinline__ void wtp_gemm(const float* __restrict__ sH2T,
                                         const float* __restrict__ sW,
                                         float* __restrict__ sWP, int tid)
{
    constexpr int NP = UW / 32;              // u-pairs per thread: 4 (UW=128) or 2
    const int te = (tid & 15) * 4;
    const int tu = (tid >> 4) * (UW / 16);
    u64 acc[4][NP];
    #pragma unroll
    for (int e = 0; e < 4; ++e)
        #pragma unroll
        for (int j = 0; j < NP; ++j) acc[e][j] = 0ull;
    #pragma unroll 4
    for (int k = 0; k < 64; ++k) {
        float4 a = *(const float4*)&sH2T[k * 64 + te];
        u64 ad[4];
        ad[0] = dupf(a.x); ad[1] = dupf(a.y); ad[2] = dupf(a.z); ad[3] = dupf(a.w);
        u64 b[NP];
        #pragma unroll
        for (int j = 0; j < NP; ++j)
            b[j] = *(const u64*)&sW[k * UW + tu + 2 * j];
        #pragma unroll
        for (int e = 0; e < 4; ++e)
            #pragma unroll
            for (int j = 0; j < NP; ++j)
                FFMA2(acc[e][j], ad[e], b[j], acc[e][j]);
    }
    #pragma unroll
    for (int e = 0; e < 4; ++e) {
        #pragma unroll
        for (int j = 0; j < NP; ++j) {
            float lo, hi; unpack2(acc[e][j], lo, hi);
            *(float2*)&sWP[(te + e) * UW + tu + 2 * j] = make_float2(lo * 0.125f, hi * 0.125f);
        }
    }
}

// ---------------------------------------------------------------------------
// Kernel B: edge MLP + tensor product + scatter-add. 64 edges/block, 256 threads.
// ---------------------------------------------------------------------------
__global__ void __launch_bounds__(256) edge_kernel(
    const float* __restrict__ edge_attr, const float* __restrict__ esa,
    const float* __restrict__ M1, const float* __restrict__ M2,
    const float* __restrict__ Wtp0, const float* __restrict__ Wtp1,
    const float* __restrict__ Wtp2, const float* __restrict__ Wtp3,
    const int* __restrict__ esrc, const int* __restrict__ edst)
{
    extern __shared__ float sm[];
    float* sInT = sm;             // 8 x 64
    float* sH1T = sm + 512;       // 64 x 64  [chan][edge]
    float* sH2T = sH1T + 4096;    // 64 x 64  [chan][edge]
    float* sW   = sH2T + 4096;    // 64 x 128 (M2 then Wtp_p)
    float* sWP  = sW + 8192;      // 64 x 128 (w outputs [edge][u])
    int*   sSrc = (int*)(sWP + 8192);
    int*   sDst = sSrc + 64;
    float* sY   = (float*)(sDst + 64);

    const int tid = threadIdx.x;
    const int eb  = blockIdx.x * 64;

    for (int idx = tid; idx < 64 * 8; idx += 256) {
        int e = idx >> 3, k = idx & 7;
        sInT[k * 64 + e] = esa[(eb + e) * 8 + k];
    }
    if (tid < 64) {
        sSrc[tid] = esrc[eb + tid];
        sDst[tid] = edst[eb + tid];
        float4 y = *(const float4*)&edge_attr[(eb + tid) * 4];
        sY[tid * 4 + 0] = y.x; sY[tid * 4 + 1] = y.y;
        sY[tid * 4 + 2] = y.z; sY[tid * 4 + 3] = y.w;
    }
    for (int idx = tid; idx < 1024; idx += 256)
        ((float4*)sW)[idx] = ((const float4*)M2)[idx];
    __syncthreads();

    // h1 = gelu((esa @ M1) / sqrt(8))
    for (int idx = tid; idx < 4096; idx += 256) {
        int u = idx >> 6, e = idx & 63;
        float s = 0.f;
        #pragma unroll
        for (int k = 0; k < 8; ++k) s += sInT[k * 64 + e] * __ldg(&M1[k * 64 + u]);
        sH1T[idx] = gelu_tanh(s * 0.3535533905932738f);
    }
    __syncthreads();

    // h2 = gelu((h1 @ M2) / sqrt(64))  — packed f32x2, u-pairs
    {
        const int e0 = (tid & 15) * 4, u0 = (tid >> 4) * 4;
        u64 acc[4][2] = {};
        #pragma unroll 4
        for (int k = 0; k < 64; ++k) {
            float4 a = *(const float4*)&sH1T[k * 64 + e0];
            u64 ad0 = dupf(a.x), ad1 = dupf(a.y), ad2 = dupf(a.z), ad3 = dupf(a.w);
            u64 b0 = *(const u64*)&sW[k * 64 + u0];
            u64 b1 = *(const u64*)&sW[k * 64 + u0 + 2];
            FFMA2(acc[0][0], ad0, b0, acc[0][0]); FFMA2(acc[0][1], ad0, b1, acc[0][1]);
            FFMA2(acc[1][0], ad1, b0, acc[1][0]); FFMA2(acc[1][1], ad1, b1, acc[1][1]);
            FFMA2(acc[2][0], ad2, b0, acc[2][0]); FFMA2(acc[2][1], ad2, b1, acc[2][1]);
            FFMA2(acc[3][0], ad3, b0, acc[3][0]); FFMA2(acc[3][1], ad3, b1, acc[3][1]);
        }
        __syncthreads();
        #pragma unroll
        for (int e = 0; e < 4; ++e)
            #pragma unroll
            for (int j = 0; j < 2; ++j) {
                float lo, hi; unpack2(acc[e][j], lo, hi);
                sH2T[(u0 + 2*j    ) * 64 + e0 + e] = gelu_tanh(lo * 0.125f);
                sH2T[(u0 + 2*j + 1) * 64 + e0 + e] = gelu_tanh(hi * 0.125f);
            }
    }
    __syncthreads();

    const int wid = tid >> 5, lane = tid & 31;
    const int lu = lane & 15, sub = lane >> 4;

    for (int p = 0; p < 4; ++p) {
        const float* Wp = (p == 0) ? Wtp0 : (p == 1) ? Wtp1 : (p == 2) ? Wtp2 : Wtp3;
        if (p < 2) {
            for (int idx = tid; idx < 2048; idx += 256)
                ((float4*)sW)[idx] = ((const float4*)Wp)[idx];
            __syncthreads();
            wtp_gemm<128>(sH2T, sW, sWP, tid);
        } else {
            for (int idx = tid; idx < 1024; idx += 256)
                ((float4*)sW)[idx] = ((const float4*)Wp)[idx];
            __syncthreads();
            wtp_gemm<64>(sH2T, sW, sWP, tid);
        }
        __syncthreads();

        if (p == 0) {
            for (int e = wid * 8; e < wid * 8 + 8; ++e) {
                int src = sSrc[e], dst = sDst[e];
                float y0 = sY[e * 4];
                float4 f = *(const float4*)&g_feat[src * 320 + lane * 4];
                float4 w = *(const float4*)&sWP[e * 128 + lane * 4];
                red4(&g_agg[dst * 768 + lane * 4],
                     make_float4(w.x*f.x*y0, w.y*f.y*y0, w.z*f.z*y0, w.w*f.w*y0));
            }
        } else if (p == 1) {
            for (int e = wid * 8; e < wid * 8 + 8; ++e) {
                int src = sSrc[e], dst = sDst[e];
                float ya = sY[e*4+1], yb = sY[e*4+2], yc = sY[e*4+3];
                float4 f = *(const float4*)&g_feat[src * 320 + lane * 4];
                float4 w = *(const float4*)&sWP[e * 128 + lane * 4];
                float t0 = w.x*f.x, t1 = w.y*f.y, t2 = w.z*f.z, t3 = w.w*f.w;
                float* base = &g_agg[dst * 768 + 192 + lane * 12];
                red4(base,     make_float4(t0*ya, t0*yb, t0*yc, t1*ya));
                red4(base + 4, make_float4(t1*yb, t1*yc, t2*ya, t2*yb));
                red4(base + 8, make_float4(t2*yc, t3*ya, t3*yb, t3*yc));
            }
        } else if (p == 2) {
            for (int s = 0; s < 4; ++s) {
                int e = wid * 8 + s * 2 + sub;
                int src = sSrc[e], dst = sDst[e];
                float y0 = sY[e * 4];
                const float* fb = &g_feat[src * 320 + 128 + lu * 12];
                float4 g0 = *(const float4*)fb;
                float4 g1 = *(const float4*)(fb + 4);
                float4 g2 = *(const float4*)(fb + 8);
                float4 w  = *(const float4*)&sWP[e * 64 + lu * 4];
                float* base = &g_agg[dst * 768 + 576 + lu * 12];
                red4(base,     make_float4(w.x*g0.x*y0, w.x*g0.y*y0, w.x*g0.z*y0, w.y*g0.w*y0));
                red4(base + 4, make_float4(w.y*g1.x*y0, w.y*g1.y*y0, w.z*g1.z*y0, w.z*g1.w*y0));
                red4(base + 8, make_float4(w.z*g2.x*y0, w.w*g2.y*y0, w.w*g2.z*y0, w.w*g2.w*y0));
            }
        } else {
            const float is3 = 0.5773502691896258f;
            for (int s = 0; s < 4; ++s) {
                int e = wid * 8 + s * 2 + sub;
                int src = sSrc[e], dst = sDst[e];
                float ya = sY[e*4+1], yb = sY[e*4+2], yc = sY[e*4+3];
                const float* fb = &g_feat[src * 320 + 128 + lu * 12];
                float4 g0 = *(const float4*)fb;
                float4 g1 = *(const float4*)(fb + 4);
                float4 g2 = *(const float4*)(fb + 8);
                float4 w  = *(const float4*)&sWP[e * 64 + lu * 4];
                float d0 = g0.x*ya + g0.y*yb + g0.z*yc;
                float d1 = g0.w*ya + g1.x*yb + g1.y*yc;
                float d2 = g1.z*ya + g1.w*yb + g2.x*yc;
                float d3 = g2.y*ya + g2.z*yb + g2.w*yc;
                red4(&g_agg[dst * 768 + 128 + lu * 4],
                     make_float4(w.x*d0*is3, w.y*d1*is3, w.z*d2*is3, w.w*d3*is3));
            }
        }
        __syncthreads();
    }
}

// ---------------------------------------------------------------------------
// Kernel D: output transforms. 32 nodes/block, 256 threads.
// ---------------------------------------------------------------------------
__global__ void __launch_bounds__(256) node_out_kernel(
    const float* __restrict__ Wo0, const float* __restrict__ Wo1,
    float* __restrict__ out)
{
    extern __shared__ float sm[];
    float* zT = sm;              // 192 x 34 (even pad)
    float* sW = sm + 192 * 34;   // 192 x 64
    const int tid = threadIdx.x;
    const int nb  = blockIdx.x * 32;
    const int n0 = (tid >> 5) * 4;    // 8 x 4 nodes
    const int u0 = (tid & 31) * 2;    // 32 x 2 u
    const float cs    = 0.9238795325112867f;   // cos(pi/8)
    const float kconv = 0.38268343236508984f * 0.25f * 0.07216878364870323f;

    // ---- scalar head: z0 = agg[:, :192] @ Wo0 ----
    for (int idx = tid; idx < 32 * 192; idx += 256) {
        int n = idx / 192, k = idx % 192;
        zT[k * 34 + n] = (nb + n < N_NODES) ? g_agg[(nb + n) * 768 + k] : 0.f;
    }
    for (int uc = 0; uc < 128; uc += 64) {
        __syncthreads();
        for (int idx = tid; idx < 192 * 64; idx += 256) {
            int k = idx >> 6, u = idx & 63;
            sW[idx] = Wo0[k * 128 + uc + u];
        }
        __syncthreads();
        u64 acc[2][2] = {};
        #pragma unroll 4
        for (int k = 0; k < 192; ++k) {
            u64 a01 = *(const u64*)&zT[k * 34 + n0];
            u64 a23 = *(const u64*)&zT[k * 34 + n0 + 2];
            float2 b = *(const float2*)&sW[k * 64 + u0];
            u64 b0 = dupf(b.x), b1 = dupf(b.y);
            FFMA2(acc[0][0], a01, b0, acc[0][0]); FFMA2(acc[0][1], a01, b1, acc[0][1]);
            FFMA2(acc[1][0], a23, b0, acc[1][0]); FFMA2(acc[1][1], a23, b1, acc[1][1]);
        }
        #pragma unroll
        for (int p = 0; p < 2; ++p) {
            float lo[2], hi[2];
            unpack2(acc[p][0], lo[0], hi[0]);
            unpack2(acc[p][1], lo[1], hi[1]);
            int na = nb + n0 + 2 * p, nc = na + 1;
            if (na < N_NODES) {
                const float* sf = &g_self[na * 320 + uc + u0];
                *(float2*)&out[na * 320 + uc + u0] =
                    make_float2(cs*sf[0] + kconv*lo[0], cs*sf[1] + kconv*lo[1]);
            }
            if (nc < N_NODES) {
                const float* sf = &g_self[nc * 320 + uc + u0];
                *(float2*)&out[nc * 320 + uc + u0] =
                    make_float2(cs*sf[0] + kconv*hi[0], cs*sf[1] + kconv*hi[1]);
            }
        }
    }

    // ---- vector head ----
    __syncthreads();
    for (int idx = tid; idx < 192 * 64; idx += 256) sW[idx] = Wo1[idx];
    for (int i = 0; i < 3; ++i) {
        __syncthreads();
        for (int idx = tid; idx < 32 * 192; idx += 256) {
            int n = idx / 192, k = idx % 192;
            zT[k * 34 + n] = (nb + n < N_NODES) ? g_agg[(nb + n) * 768 + 192 + k * 3 + i] : 0.f;
        }
        __syncthreads();
        u64 acc[2][2] = {};
        #pragma unroll 4
        for (int k = 0; k < 192; ++k) {
            u64 a01 = *(const u64*)&zT[k * 34 + n0];
            u64 a23 = *(const u64*)&zT[k * 34 + n0 + 2];
            float2 b = *(const float2*)&sW[k * 64 + u0];
            u64 b0 = dupf(b.x), b1 = dupf(b.y);
            FFMA2(acc[0][0], a01, b0, acc[0][0]); FFMA2(acc[0][1], a01, b1, acc[0][1]);
            FFMA2(acc[1][0], a23, b0, acc[1][0]); FFMA2(acc[1][1], a23, b1, acc[1][1]);
        }
        #pragma unroll
        for (int p = 0; p < 2; ++p) {
            float lo[2], hi[2];
            unpack2(acc[p][0], lo[0], hi[0]);
            unpack2(acc[p][1], lo[1], hi[1]);
            int na = nb + n0 + 2 * p, nc = na + 1;
            #pragma unroll
            for (int j = 0; j < 2; ++j) {
                if (na < N_NODES)
                    out[na * 320 + 128 + (u0 + j) * 3 + i] =
                        cs * g_self[na * 320 + 128 + (u0 + j) * 3 + i] + kconv * lo[j];
                if (nc < N_NODES)
                    out[nc * 320 + 128 + (u0 + j) * 3 + i] =
                        cs * g_self[nc * 320 + 128 + (u0 + j) * 3 + i] + kconv * hi[j];
            }
        }
    }
}

// ---------------------------------------------------------------------------
extern "C" void kernel_launch(void* const* d_in, const int* in_sizes, int n_in,
                              void* d_out, int out_size)
{
    const float* node = (const float*)d_in[0];
    const float* edge_attr = (const float*)d_in[1];
    const float* esa  = (const float*)d_in[2];
    const float* Wa0  = (const float*)d_in[3];
    const float* Wa1  = (const float*)d_in[4];
    const float* Wb0  = (const float*)d_in[5];
    const float* Wb1  = (const float*)d_in[6];
    const float* M1   = (const float*)d_in[7];
    const float* M2   = (const float*)d_in[8];
    const float* Wtp0 = (const float*)d_in[9];
    const float* Wtp1 = (const float*)d_in[10];
    const float* Wtp2 = (const float*)d_in[11];
    const float* Wtp3 = (const float*)d_in[12];
    const float* Wo0  = (const float*)d_in[13];
    const float* Wo1  = (const float*)d_in[14];
    const int* esrc   = (const int*)d_in[15];
    const int* edst   = (const int*)d_in[16];
    float* out = (float*)d_out;

    const int smemA = (320 * 34 + 128 * 128) * 4;                 // 109056
    const int smemB = (512 + 4096 + 4096 + 8192 + 8192) * 4 + 64 * 4 * 2 + 64 * 4 * 4; // 101888
    const int smemD = (192 * 34 + 192 * 64) * 4;                  // 75264

    cudaFuncSetAttribute(node_pre_kernel, cudaFuncAttributeMaxDynamicSharedMemorySize, smemA);
    cudaFuncSetAttribute(edge_kernel,     cudaFuncAttributeMaxDynamicSharedMemorySize, smemB);
    cudaFuncSetAttribute(node_out_kernel, cudaFuncAttributeMaxDynamicSharedMemorySize, smemD);

    void* aggp = nullptr;
    cudaGetSymbolAddress(&aggp, g_agg);
    cudaMemsetAsync(aggp, 0, sizeof(float) * (size_t)N_NODES * AGG_DIM);

    node_pre_kernel<<<(N_NODES + 31) / 32, 256, smemA>>>(node, Wa0, Wa1, Wb0, Wb1);
    edge_kernel<<<N_EDGES / 64, 256, smemB>>>(edge_attr, esa, M1, M2,
                                              Wtp0, Wtp1, Wtp2, Wtp3, esrc, edst);
    node_out_kernel<<<(N_NODES + 31) / 32, 256, smemD>>>(Wo0, Wo1, out);
}